// round 9
// baseline (speedup 1.0000x reference)
#include <cuda_runtime.h>
#include <math.h>

namespace {

constexpr int B = 128;
constexpr int N = 2048;
constexpr int E = 32768;
constexpr int BN = B * N;             // 262144 nodes
constexpr int CAP = 64;               // max edges per node (Poisson(16), 12-sigma safe)
constexpr float INV_SQRT_DH = 0.7071067811865476f;

// Scratch (device globals — no allocations allowed)
__device__ float g_h[BN * 4];          // node state (h1 then h2), 4 MB
__device__ int   g_cursor[BN];         // per-node degree counter, 1 MB
__device__ int2  g_payload[CAP * BN];  // slot-major edge buckets (src, time), 134 MB

// Weights in constant memory (filled by capturable D2D copies each launch)
__constant__ float cWq[2 * 16];
__constant__ float cWk[2 * 32];
__constant__ float cWv[2 * 32];
__constant__ float cWo[2 * 16];
__constant__ float cbo[2 * 4];
__constant__ float ctw[4];
__constant__ float ctb[4];
__constant__ float cWlin[24];
__constant__ float cblin[2];

// ---------------------------------------------------------------------------
// Zero the degree counters. 256 blocks x 256 threads x int4.
// ---------------------------------------------------------------------------
__global__ void __launch_bounds__(256) zero_cursor() {
    int idx = blockIdx.x * blockDim.x + threadIdx.x;
    reinterpret_cast<int4*>(g_cursor)[idx] = make_int4(0, 0, 0, 0);
}

// ---------------------------------------------------------------------------
// Scatter: bucket every edge by dst. 4 edges per thread with vector loads.
// 1 scalar RED (cursor) + 1 STG.64 (payload) per edge.
// ---------------------------------------------------------------------------
constexpr int SC_THREADS = 256;
constexpr int SC_EPT = 4;                          // edges per thread
constexpr int SC_GROUPS_PER_B = E / SC_EPT;        // 8192 = 2^13

__global__ void __launch_bounds__(SC_THREADS) scatter_kernel(
        const int*   __restrict__ edge_index,
        const float* __restrict__ edge_time) {
    int gid = blockIdx.x * SC_THREADS + threadIdx.x;   // 0 .. B*E/4-1
    int b = gid >> 13;
    int e = (gid & (SC_GROUPS_PER_B - 1)) * SC_EPT;

    const int* ei = edge_index + (size_t)b * 2 * E;
    int4   s4 = __ldg(reinterpret_cast<const int4*>(ei + e));
    int4   d4 = __ldg(reinterpret_cast<const int4*>(ei + E + e));
    float4 t4 = __ldg(reinterpret_cast<const float4*>(edge_time + (size_t)b * E + e));

    int nb = b * N;

    int src[4] = {s4.x, s4.y, s4.z, s4.w};
    int dst[4] = {d4.x, d4.y, d4.z, d4.w};
    float tt[4] = {t4.x, t4.y, t4.z, t4.w};
#pragma unroll
    for (int i = 0; i < 4; i++) {
        int node = nb + dst[i];
        int pos = atomicAdd(&g_cursor[node], 1);
        if (pos < CAP) {
            g_payload[(size_t)pos * BN + node] =
                make_int2(src[i], __float_as_int(tt[i]));
        }
    }
}

// ---------------------------------------------------------------------------
// Gather pass for layer L: stage per-batch kh/vh tiles (64 KB) in smem, then
// each thread owns one dst node: walk its bucket, accumulate softmax in
// registers, and write the fused node update. Zero atomics.
// ---------------------------------------------------------------------------
constexpr int G_THREADS = 256;
constexpr int GPB = N / G_THREADS;     // 8 blocks per batch
constexpr int G_SMEM = 2 * N * 16;     // 64 KB

template <int L>
__global__ void __launch_bounds__(G_THREADS) gather_pass(
        const float* __restrict__ x,
        const float* __restrict__ timestamp) {
    extern __shared__ float4 smem[];
    float4* skh = smem;        // h@Wk_top per node
    float4* svh = smem + N;    // h@Wv_top per node

    int b     = blockIdx.x >> 3;
    int chunk = blockIdx.x & 7;

    const float4* hsrc = (L == 0 ? reinterpret_cast<const float4*>(x)
                                 : reinterpret_cast<const float4*>(g_h)) + b * N;

    const float* WkT = cWk + L * 32;        // rows 0..3 (h part)
    const float* WvT = cWv + L * 32;
    const float* WkB = cWk + L * 32 + 16;   // rows 4..7 (phi part)
    const float* WvB = cWv + L * 32 + 16;
    const float* Wq  = cWq + L * 16;

    // Stage kh/vh for the whole batch (coalesced reads, tiny redundant FMA).
    for (int i = threadIdx.x; i < N; i += G_THREADS) {
        float4 h = hsrc[i];
        float kh[4], vh[4];
#pragma unroll
        for (int j = 0; j < 4; j++) {
            float a = h.x * WkT[0 * 4 + j];
            a = fmaf(h.y, WkT[1 * 4 + j], a);
            a = fmaf(h.z, WkT[2 * 4 + j], a);
            a = fmaf(h.w, WkT[3 * 4 + j], a);
            kh[j] = a;
            float c = h.x * WvT[0 * 4 + j];
            c = fmaf(h.y, WvT[1 * 4 + j], c);
            c = fmaf(h.z, WvT[2 * 4 + j], c);
            c = fmaf(h.w, WvT[3 * 4 + j], c);
            vh[j] = c;
        }
        skh[i] = make_float4(kh[0], kh[1], kh[2], kh[3]);
        svh[i] = make_float4(vh[0], vh[1], vh[2], vh[3]);
    }
    __syncthreads();

    int n = chunk * G_THREADS + threadIdx.x;
    int gnode = b * N + n;

    float4 hn = hsrc[n];
    float q[4];
#pragma unroll
    for (int j = 0; j < 4; j++) {
        float a = hn.x * Wq[0 * 4 + j];
        a = fmaf(hn.y, Wq[1 * 4 + j], a);
        a = fmaf(hn.z, Wq[2 * 4 + j], a);
        a = fmaf(hn.w, Wq[3 * 4 + j], a);
        q[j] = a * INV_SQRT_DH;
    }

    int deg = min(g_cursor[gnode], CAP);
    float ts = __ldg(timestamp + b);

    float s0 = 0.f, s1 = 0.f;
    float a0 = 0.f, a1 = 0.f, a2 = 0.f, a3 = 0.f;

    for (int i = 0; i < deg; i++) {
        int2 pl = g_payload[(size_t)i * BN + gnode];
        int src = pl.x;
        float dt = ts - __int_as_float(pl.y);

        float phi[4];
#pragma unroll
        for (int j = 0; j < 4; j++) phi[j] = __cosf(fmaf(dt, ctw[j], ctb[j]));

        float4 kh4 = skh[src];
        float k0 = kh4.x, k1 = kh4.y, k2 = kh4.z, k3 = kh4.w;
#pragma unroll
        for (int j = 0; j < 4; j++) {
            k0 = fmaf(phi[j], WkB[j * 4 + 0], k0);
            k1 = fmaf(phi[j], WkB[j * 4 + 1], k1);
            k2 = fmaf(phi[j], WkB[j * 4 + 2], k2);
            k3 = fmaf(phi[j], WkB[j * 4 + 3], k3);
        }

        float l0 = fmaf(q[0], k0, q[1] * k1);
        float l1 = fmaf(q[2], k2, q[3] * k3);
        float p0 = __expf(fminf(l0, 80.0f));
        float p1 = __expf(fminf(l1, 80.0f));

        float4 vh4 = svh[src];
        float v0 = vh4.x, v1 = vh4.y, v2 = vh4.z, v3 = vh4.w;
#pragma unroll
        for (int j = 0; j < 4; j++) {
            v0 = fmaf(phi[j], WvB[j * 4 + 0], v0);
            v1 = fmaf(phi[j], WvB[j * 4 + 1], v1);
            v2 = fmaf(phi[j], WvB[j * 4 + 2], v2);
            v3 = fmaf(phi[j], WvB[j * 4 + 3], v3);
        }

        s0 += p0;
        s1 += p1;
        a0 = fmaf(p0, v0, a0);
        a1 = fmaf(p0, v1, a1);
        a2 = fmaf(p1, v2, a2);
        a3 = fmaf(p1, v3, a3);
    }

    // Fused node update: h_next = relu(h + (agg/s) @ Wo + bo)
    float r0 = (s0 == 0.0f) ? 1.0f : __frcp_rn(s0);
    float r1 = (s1 == 0.0f) ? 1.0f : __frcp_rn(s1);
    float at0 = a0 * r0, at1 = a1 * r0;
    float at2 = a2 * r1, at3 = a3 * r1;

    const float* Wo = cWo + L * 16;
    const float* bo = cbo + L * 4;
    float hin[4] = {hn.x, hn.y, hn.z, hn.w};
    float hout[4];
#pragma unroll
    for (int j = 0; j < 4; j++) {
        float v = hin[j] + bo[j];
        v = fmaf(at0, Wo[0 * 4 + j], v);
        v = fmaf(at1, Wo[1 * 4 + j], v);
        v = fmaf(at2, Wo[2 * 4 + j], v);
        v = fmaf(at3, Wo[3 * 4 + j], v);
        hout[j] = fmaxf(v, 0.0f);
    }
    reinterpret_cast<float4*>(g_h)[gnode] =
        make_float4(hout[0], hout[1], hout[2], hout[3]);
}

// ---------------------------------------------------------------------------
// Final head: feats = [h[src_idx], h[dst_idx], cos(ts*w+b)] @ W_lin + b_lin
// ---------------------------------------------------------------------------
__global__ void final_kernel(const int*   __restrict__ src_index,
                             const int*   __restrict__ dst_index,
                             const float* __restrict__ timestamp,
                             float* __restrict__ out) {
    int b = threadIdx.x;
    if (b >= B) return;

    float4 hs = reinterpret_cast<const float4*>(g_h)[b * N + src_index[b]];
    float4 hd = reinterpret_cast<const float4*>(g_h)[b * N + dst_index[b]];
    float ts = timestamp[b];

    float f[12];
    f[0] = hs.x; f[1] = hs.y; f[2] = hs.z; f[3] = hs.w;
    f[4] = hd.x; f[5] = hd.y; f[6] = hd.z; f[7] = hd.w;
#pragma unroll
    for (int j = 0; j < 4; j++) f[8 + j] = cosf(fmaf(ts, ctw[j], ctb[j]));

#pragma unroll
    for (int k = 0; k < 2; k++) {
        float acc = cblin[k];
#pragma unroll
        for (int i = 0; i < 12; i++) acc = fmaf(f[i], cWlin[i * 2 + k], acc);
        out[b * 2 + k] = acc;
    }
}

} // anonymous namespace

extern "C" void kernel_launch(void* const* d_in, const int* in_sizes, int n_in,
                              void* d_out, int out_size) {
    const float* x          = (const float*)d_in[0];
    const int*   edge_index = (const int*)  d_in[1];
    const float* edge_time  = (const float*)d_in[2];
    const float* timestamp  = (const float*)d_in[3];
    const int*   src_index  = (const int*)  d_in[4];
    const int*   dst_index  = (const int*)  d_in[5];
    float* out = (float*)d_out;

    // Allow 64 KB dynamic smem for the gather kernels (host-side, idempotent).
    static bool attr_set = false;
    if (!attr_set) {
        cudaFuncSetAttribute(gather_pass<0>,
            cudaFuncAttributeMaxDynamicSharedMemorySize, G_SMEM);
        cudaFuncSetAttribute(gather_pass<1>,
            cudaFuncAttributeMaxDynamicSharedMemorySize, G_SMEM);
        attr_set = true;
    }

    // Stage all weights into constant memory (device-to-device, capturable).
    cudaMemcpyToSymbolAsync(cWq,   d_in[8],  2 * 16 * 4, 0, cudaMemcpyDeviceToDevice);
    cudaMemcpyToSymbolAsync(cWk,   d_in[9],  2 * 32 * 4, 0, cudaMemcpyDeviceToDevice);
    cudaMemcpyToSymbolAsync(cWv,   d_in[10], 2 * 32 * 4, 0, cudaMemcpyDeviceToDevice);
    cudaMemcpyToSymbolAsync(cWo,   d_in[11], 2 * 16 * 4, 0, cudaMemcpyDeviceToDevice);
    cudaMemcpyToSymbolAsync(cbo,   d_in[12], 2 * 4 * 4,  0, cudaMemcpyDeviceToDevice);
    cudaMemcpyToSymbolAsync(ctw,   d_in[6],  4 * 4,      0, cudaMemcpyDeviceToDevice);
    cudaMemcpyToSymbolAsync(ctb,   d_in[7],  4 * 4,      0, cudaMemcpyDeviceToDevice);
    cudaMemcpyToSymbolAsync(cWlin, d_in[13], 24 * 4,     0, cudaMemcpyDeviceToDevice);
    cudaMemcpyToSymbolAsync(cblin, d_in[14], 2 * 4,      0, cudaMemcpyDeviceToDevice);

    zero_cursor<<<BN / (256 * 4), 256>>>();

    scatter_kernel<<<(B * E) / (SC_THREADS * SC_EPT), SC_THREADS>>>(
        edge_index, edge_time);

    gather_pass<0><<<B * GPB, G_THREADS, G_SMEM>>>(x, timestamp);
    gather_pass<1><<<B * GPB, G_THREADS, G_SMEM>>>(x, timestamp);

    final_kernel<<<1, 128>>>(src_index, dst_index, timestamp, out);
}